// round 2
// baseline (speedup 1.0000x reference)
#include <cuda_runtime.h>
#include <math.h>

#define HW 224
#define C 96
#define T 49
#define CQKV 288
#define HID 384
#define HCH 192

#define XSTR 100
#define SSTR 52
#define WSTR 292
#define HSTR 196

#define OFF_QKV (T*XSTR)                 /* 4900  */
#define OFF_S   (OFF_QKV + 3*T*XSTR)     /* 19600 */
#define OFF_W   (OFF_S + T*SSTR)         /* 22148 */
#define SMEM_FLOATS (OFF_W + 8*WSTR)     /* 24484 */
#define SMEM_BYTES (SMEM_FLOATS * 4)     /* 97936 */

__global__ __launch_bounds__(256, 2)
void swin_fused(const float* __restrict__ x, const float* __restrict__ qkv_w,
                const float* __restrict__ ln_w, const float* __restrict__ ln_b,
                const float* __restrict__ w1, const float* __restrict__ b1,
                const float* __restrict__ w2, const float* __restrict__ b2,
                float* __restrict__ out)
{
    extern __shared__ float sm[];
    float* XLN = sm;                    // [49][100] : x_ln, later attn_out
    float* Qs  = sm + OFF_QKV;          // [49][100]
    float* Ks  = Qs + T*XSTR;
    float* Vs  = Ks + T*XSTR;
    float* Ss  = sm + OFF_S;            // [49][52]
    float* Wst = sm + OFF_W;            // weight staging
    float* HB  = sm + OFF_QKV;          // [49][196] hidden buffer (reuses Q/K)

    const int tid  = threadIdx.x;
    const int widx = blockIdx.x;
    const int b  = widx >> 10;
    const int wh = (widx >> 5) & 31;
    const int ww = widx & 31;
    const size_t base = ((size_t)(b*HW + wh*7) * HW + (size_t)(ww*7)) * C;

    // ---- load x window (49 x 96) ----
    for (int i = tid; i < T*24; i += 256) {
        int t = i / 24, v4 = i - t*24;
        int r = t / 7, s = t - r*7;
        float4 val = *(const float4*)(x + base + (size_t)(r*HW + s)*C + v4*4);
        *(float4*)(XLN + t*XSTR + v4*4) = val;
    }
    __syncthreads();

    // ---- layernorm (warp per row set) ----
    {
        const int lane = tid & 31, warp = tid >> 5;
        const float lw0 = ln_w[lane], lw1 = ln_w[lane+32], lw2 = ln_w[lane+64];
        const float lb0 = ln_b[lane], lb1 = ln_b[lane+32], lb2 = ln_b[lane+64];
        for (int t = warp; t < T; t += 8) {
            float a0 = XLN[t*XSTR+lane], a1 = XLN[t*XSTR+lane+32], a2 = XLN[t*XSTR+lane+64];
            float sum = a0+a1+a2;
            float sq  = a0*a0 + a1*a1 + a2*a2;
            #pragma unroll
            for (int o = 16; o; o >>= 1) {
                sum += __shfl_xor_sync(0xffffffffu, sum, o);
                sq  += __shfl_xor_sync(0xffffffffu, sq , o);
            }
            float mu  = sum * (1.f/96.f);
            float var = fmaxf(sq * (1.f/96.f) - mu*mu, 0.f);
            float rs  = rsqrtf(var + 1e-5f);
            XLN[t*XSTR+lane]    = (a0-mu)*rs*lw0 + lb0;
            XLN[t*XSTR+lane+32] = (a1-mu)*rs*lw1 + lb1;
            XLN[t*XSTR+lane+64] = (a2-mu)*rs*lw2 + lb2;
        }
    }
    __syncthreads();

    // ---- QKV GEMM: [49x96] @ [96x288], staged weights, 7x8 register tile ----
    {
        const int cg = tid % 36, tg = tid / 36;    // tg<7 active (252 threads)
        float acc[7][8];
        #pragma unroll
        for (int i=0;i<7;i++)
            #pragma unroll
            for (int j=0;j<8;j++) acc[i][j] = 0.f;
        for (int c0 = 0; c0 < C; c0 += 8) {
            for (int i = tid; i < 576; i += 256) {              // 8 rows x 288 cols
                int cc = i / 72, j4 = i - cc*72;
                *(float4*)(Wst + cc*WSTR + j4*4) =
                    *(const float4*)(qkv_w + (size_t)(c0+cc)*CQKV + j4*4);
            }
            __syncthreads();
            if (tg < 7) {
                #pragma unroll
                for (int cc = 0; cc < 8; cc++) {
                    float xv[7];
                    #pragma unroll
                    for (int i=0;i<7;i++) xv[i] = XLN[(tg*7+i)*XSTR + c0 + cc];
                    float4 wa = *(float4*)(Wst + cc*WSTR + cg*8);
                    float4 wb = *(float4*)(Wst + cc*WSTR + cg*8 + 4);
                    float wv[8] = {wa.x,wa.y,wa.z,wa.w,wb.x,wb.y,wb.z,wb.w};
                    #pragma unroll
                    for (int i=0;i<7;i++)
                        #pragma unroll
                        for (int j=0;j<8;j++)
                            acc[i][j] = fmaf(xv[i], wv[j], acc[i][j]);
                }
            }
            __syncthreads();
        }
        if (tg < 7) {
            const int j0 = cg*8;
            float* dst = (j0 < 96) ? Qs : (j0 < 192 ? Ks : Vs);
            const int jl = j0 % 96;
            #pragma unroll
            for (int i=0;i<7;i++)
                #pragma unroll
                for (int j=0;j<8;j++)
                    dst[(tg*7+i)*XSTR + jl + j] = acc[i][j];
        }
    }
    __syncthreads();

    // ---- logits S = Q K^T / sqrt(96) ----
    {
        const float scale = 0.10206207261596577f;
        for (int u = tid; u < 343; u += 256) {
            int n = u / 7, mg = u - n*7;
            float acc[7] = {0,0,0,0,0,0,0};
            for (int c = 0; c < C; c++) {
                float qv = Qs[n*XSTR + c];
                #pragma unroll
                for (int mm=0;mm<7;mm++)
                    acc[mm] = fmaf(qv, Ks[(mg*7+mm)*XSTR + c], acc[mm]);
            }
            #pragma unroll
            for (int mm=0;mm<7;mm++) Ss[n*SSTR + mg*7+mm] = acc[mm]*scale;
        }
    }
    __syncthreads();

    // ---- softmax rows ----
    {
        const int lane = tid & 31, warp = tid >> 5;
        for (int n = warp; n < T; n += 8) {
            float v0 = Ss[n*SSTR + lane];
            float v1 = (lane < 17) ? Ss[n*SSTR + 32 + lane] : -3.0e38f;
            float m = fmaxf(v0, v1);
            #pragma unroll
            for (int o=16;o;o>>=1) m = fmaxf(m, __shfl_xor_sync(0xffffffffu, m, o));
            float e0 = __expf(v0 - m);
            float e1 = (lane < 17) ? __expf(v1 - m) : 0.f;
            float ssum = e0 + e1;
            #pragma unroll
            for (int o=16;o;o>>=1) ssum += __shfl_xor_sync(0xffffffffu, ssum, o);
            float inv = 1.f / ssum;
            Ss[n*SSTR + lane] = e0*inv;
            if (lane < 17) Ss[n*SSTR + 32 + lane] = e1*inv;
        }
    }
    __syncthreads();

    // ---- attn_out = S @ V -> XLN ----
    {
        const int cg = tid % 24, tg = tid / 24;    // tg<7 active (168 threads)
        if (tg < 7) {
            float acc[7][4];
            #pragma unroll
            for (int i=0;i<7;i++){acc[i][0]=acc[i][1]=acc[i][2]=acc[i][3]=0.f;}
            for (int m = 0; m < T; m++) {
                float sv[7];
                #pragma unroll
                for (int i=0;i<7;i++) sv[i] = Ss[(tg*7+i)*SSTR + m];
                float4 vv = *(float4*)(Vs + m*XSTR + cg*4);
                #pragma unroll
                for (int i=0;i<7;i++) {
                    acc[i][0] = fmaf(sv[i], vv.x, acc[i][0]);
                    acc[i][1] = fmaf(sv[i], vv.y, acc[i][1]);
                    acc[i][2] = fmaf(sv[i], vv.z, acc[i][2]);
                    acc[i][3] = fmaf(sv[i], vv.w, acc[i][3]);
                }
            }
            #pragma unroll
            for (int i=0;i<7;i++) {
                float* d = XLN + (tg*7+i)*XSTR + cg*4;
                d[0]=acc[i][0]; d[1]=acc[i][1]; d[2]=acc[i][2]; d[3]=acc[i][3];
            }
        }
    }
    __syncthreads();

    // ---- MLP: two hidden chunks of 192, persistent output accumulators ----
    const int cg = tid % 24, tg = tid / 24;
    float facc[7][4];
    #pragma unroll
    for (int i=0;i<7;i++){facc[i][0]=facc[i][1]=facc[i][2]=facc[i][3]=0.f;}

    for (int hc = 0; hc < 2; hc++) {
        const int j0 = hc * HCH;
        // hidden = gelu(attn_out @ w1[:, j0:j0+192] + b1)
        {
            float hacc[7][8];
            #pragma unroll
            for (int i=0;i<7;i++)
                #pragma unroll
                for (int j=0;j<8;j++) hacc[i][j] = 0.f;
            for (int c0 = 0; c0 < C; c0 += 8) {
                for (int i = tid; i < 384; i += 256) {          // 8 rows x 192 cols
                    int cc = i / 48, j4 = i - cc*48;
                    *(float4*)(Wst + cc*WSTR + j4*4) =
                        *(const float4*)(w1 + (size_t)(c0+cc)*HID + j0 + j4*4);
                }
                __syncthreads();
                if (tg < 7) {
                    #pragma unroll
                    for (int cc=0;cc<8;cc++) {
                        float av[7];
                        #pragma unroll
                        for (int i=0;i<7;i++) av[i] = XLN[(tg*7+i)*XSTR + c0+cc];
                        float4 wa = *(float4*)(Wst + cc*WSTR + cg*8);
                        float4 wb = *(float4*)(Wst + cc*WSTR + cg*8 + 4);
                        float wv[8] = {wa.x,wa.y,wa.z,wa.w,wb.x,wb.y,wb.z,wb.w};
                        #pragma unroll
                        for (int i=0;i<7;i++)
                            #pragma unroll
                            for (int j=0;j<8;j++)
                                hacc[i][j] = fmaf(av[i], wv[j], hacc[i][j]);
                    }
                }
                __syncthreads();
            }
            if (tg < 7) {
                float4 ba = *(const float4*)(b1 + j0 + cg*8);
                float4 bbv = *(const float4*)(b1 + j0 + cg*8 + 4);
                float bv[8] = {ba.x,ba.y,ba.z,ba.w,bbv.x,bbv.y,bbv.z,bbv.w};
                #pragma unroll
                for (int i=0;i<7;i++)
                    #pragma unroll
                    for (int j=0;j<8;j++) {
                        float h = hacc[i][j] + bv[j];
                        float g = 0.5f * h * (1.f + erff(h * 0.70710678118654752f));
                        HB[(tg*7+i)*HSTR + cg*8 + j] = g;
                    }
            }
        }
        __syncthreads();
        // facc += hidden @ w2[j0:j0+192, :]
        for (int k0 = 0; k0 < HCH; k0 += 16) {
            for (int i = tid; i < 384; i += 256) {              // 16 rows x 96 cols
                int kk = i / 24, c4 = i - kk*24;
                *(float4*)(Wst + kk*96 + c4*4) =
                    *(const float4*)(w2 + (size_t)(j0+k0+kk)*C + c4*4);
            }
            __syncthreads();
            if (tg < 7) {
                #pragma unroll
                for (int kk=0;kk<16;kk++) {
                    float hv[7];
                    #pragma unroll
                    for (int i=0;i<7;i++) hv[i] = HB[(tg*7+i)*HSTR + k0 + kk];
                    float4 wv = *(float4*)(Wst + kk*96 + cg*4);
                    #pragma unroll
                    for (int i=0;i<7;i++) {
                        facc[i][0] = fmaf(hv[i], wv.x, facc[i][0]);
                        facc[i][1] = fmaf(hv[i], wv.y, facc[i][1]);
                        facc[i][2] = fmaf(hv[i], wv.z, facc[i][2]);
                        facc[i][3] = fmaf(hv[i], wv.w, facc[i][3]);
                    }
                }
            }
            __syncthreads();
        }
    }

    // ---- epilogue: + b2 + residual(attn_out), store ----
    if (tg < 7) {
        float4 bb = *(const float4*)(b2 + cg*4);
        #pragma unroll
        for (int i=0;i<7;i++) {
            int t = tg*7 + i;                 // r = tg, s = i
            const float* ao = XLN + t*XSTR + cg*4;
            float4 o;
            o.x = facc[i][0] + bb.x + ao[0];
            o.y = facc[i][1] + bb.y + ao[1];
            o.z = facc[i][2] + bb.z + ao[2];
            o.w = facc[i][3] + bb.w + ao[3];
            *(float4*)(out + base + (size_t)(tg*HW + i)*C + cg*4) = o;
        }
    }
}

extern "C" void kernel_launch(void* const* d_in, const int* in_sizes, int n_in,
                              void* d_out, int out_size) {
    cudaFuncSetAttribute(swin_fused, cudaFuncAttributeMaxDynamicSharedMemorySize, SMEM_BYTES);
    swin_fused<<<8192, 256, SMEM_BYTES>>>(
        (const float*)d_in[0], (const float*)d_in[1], (const float*)d_in[2],
        (const float*)d_in[3], (const float*)d_in[4], (const float*)d_in[5],
        (const float*)d_in[6], (const float*)d_in[7], (float*)d_out);
}

// round 4
// speedup vs baseline: 1.3262x; 1.3262x over previous
#include <cuda_runtime.h>
#include <math.h>

#define HW 224
#define C 96
#define T 49
#define CQKV 288
#define HID 384
#define HCH 192

#define XSTR 100
#define SSTR 52
#define WSTR 292
#define W1STR 196
#define W2STR 100
#define HSTR 196

#define OFF_QKV (T*XSTR)                 /* 4900  */
#define OFF_S   (OFF_QKV + 3*T*XSTR)     /* 19600 */
#define OFF_W   (OFF_S + T*SSTR)         /* 22148 */
#define SMEM_FLOATS (OFF_W + 16*WSTR)    /* 26820 */
#define SMEM_BYTES (SMEM_FLOATS * 4)     /* 107280 */

typedef unsigned long long u64t;

__device__ __forceinline__ u64t splat2(float a){
    u64t r; asm("mov.b64 %0, {%1,%1};" : "=l"(r) : "f"(a)); return r;
}
__device__ __forceinline__ u64t pk2(float a, float b){
    u64t r; asm("mov.b64 %0, {%1,%2};" : "=l"(r) : "f"(a), "f"(b)); return r;
}
__device__ __forceinline__ u64t fma2(u64t a, u64t b, u64t c){
    u64t d; asm("fma.rn.f32x2 %0, %1, %2, %3;" : "=l"(d) : "l"(a), "l"(b), "l"(c)); return d;
}
__device__ __forceinline__ void up2(u64t x, float& l, float& h){
    asm("mov.b64 {%0,%1}, %2;" : "=f"(l), "=f"(h) : "l"(x));
}

__global__ __launch_bounds__(256, 2)
void swin_fused(const float* __restrict__ x, const float* __restrict__ qkv_w,
                const float* __restrict__ ln_w, const float* __restrict__ ln_b,
                const float* __restrict__ w1, const float* __restrict__ b1,
                const float* __restrict__ w2, const float* __restrict__ b2,
                float* __restrict__ out)
{
    extern __shared__ float sm[];
    float* XLN = sm;                    // [49][100] : x_ln, later attn_out
    float* Qs  = sm + OFF_QKV;          // [49][100]
    float* Ks  = Qs + T*XSTR;
    float* Vs  = Ks + T*XSTR;
    float* Ss  = sm + OFF_S;            // [49][52]
    float* Wst = sm + OFF_W;            // weight staging (16*292 floats)
    float* HB  = sm + OFF_QKV;          // hidden buffer [<=56][196] (reuses Q/K/V)

    const int tid  = threadIdx.x;
    const int widx = blockIdx.x;
    const int b  = widx >> 10;
    const int wh = (widx >> 5) & 31;
    const int ww = widx & 31;
    const size_t base = ((size_t)(b*HW + wh*7) * HW + (size_t)(ww*7)) * C;

    // ---- load x window (49 x 96) ----
    for (int i = tid; i < T*24; i += 256) {
        int t = i / 24, v4 = i - t*24;
        int r = t / 7, s = t - r*7;
        float4 val = *(const float4*)(x + base + (size_t)(r*HW + s)*C + v4*4);
        *(float4*)(XLN + t*XSTR + v4*4) = val;
    }
    __syncthreads();

    // ---- layernorm ----
    {
        const int lane = tid & 31, warp = tid >> 5;
        const float lw0 = ln_w[lane], lw1 = ln_w[lane+32], lw2 = ln_w[lane+64];
        const float lb0 = ln_b[lane], lb1 = ln_b[lane+32], lb2 = ln_b[lane+64];
        for (int t = warp; t < T; t += 8) {
            float a0 = XLN[t*XSTR+lane], a1 = XLN[t*XSTR+lane+32], a2 = XLN[t*XSTR+lane+64];
            float sum = a0+a1+a2;
            float sq  = a0*a0 + a1*a1 + a2*a2;
            #pragma unroll
            for (int o = 16; o; o >>= 1) {
                sum += __shfl_xor_sync(0xffffffffu, sum, o);
                sq  += __shfl_xor_sync(0xffffffffu, sq , o);
            }
            float mu  = sum * (1.f/96.f);
            float var = fmaxf(sq * (1.f/96.f) - mu*mu, 0.f);
            float rs  = rsqrtf(var + 1e-5f);
            XLN[t*XSTR+lane]    = (a0-mu)*rs*lw0 + lb0;
            XLN[t*XSTR+lane+32] = (a1-mu)*rs*lw1 + lb1;
            XLN[t*XSTR+lane+64] = (a2-mu)*rs*lw2 + lb2;
        }
    }
    __syncthreads();

    // ---- QKV GEMM: [49x96] @ [96x288], f32x2, 7x8 tile (j-packed) ----
    {
        const int cg = tid % 36, tg = tid / 36;    // tg<7 active
        u64t acc[7][4];
        #pragma unroll
        for (int i=0;i<7;i++)
            #pragma unroll
            for (int p=0;p<4;p++) acc[i][p] = 0ull;
        for (int c0 = 0; c0 < C; c0 += 16) {
            for (int i = tid; i < 1152; i += 256) {            // 16 rows x 288 cols
                int cc = i / 72, j4 = i - cc*72;
                *(float4*)(Wst + cc*WSTR + j4*4) =
                    *(const float4*)(qkv_w + (size_t)(c0+cc)*CQKV + j4*4);
            }
            __syncthreads();
            if (tg < 7) {
                #pragma unroll 4
                for (int cc = 0; cc < 16; cc++) {
                    u64t xs[7];
                    #pragma unroll
                    for (int i=0;i<7;i++) xs[i] = splat2(XLN[(tg*7+i)*XSTR + c0 + cc]);
                    const u64t* wp = (const u64t*)(Wst + cc*WSTR + cg*8);
                    u64t w0=wp[0], w1v=wp[1], w2v=wp[2], w3v=wp[3];
                    #pragma unroll
                    for (int i=0;i<7;i++) {
                        acc[i][0] = fma2(xs[i], w0, acc[i][0]);
                        acc[i][1] = fma2(xs[i], w1v, acc[i][1]);
                        acc[i][2] = fma2(xs[i], w2v, acc[i][2]);
                        acc[i][3] = fma2(xs[i], w3v, acc[i][3]);
                    }
                }
            }
            __syncthreads();
        }
        if (tg < 7) {
            const int j0 = cg*8;
            float* dst = (j0 < 96) ? Qs : (j0 < 192 ? Ks : Vs);
            const int jl = j0 % 96;
            #pragma unroll
            for (int i=0;i<7;i++)
                #pragma unroll
                for (int p=0;p<4;p++) {
                    float l,h; up2(acc[i][p], l, h);
                    dst[(tg*7+i)*XSTR + jl + 2*p]   = l;
                    dst[(tg*7+i)*XSTR + jl + 2*p+1] = h;
                }
        }
    }
    __syncthreads();

    // ---- logits S = Q K^T / sqrt(96), contraction-packed f32x2 ----
    {
        const float scale = 0.10206207261596577f;
        for (int u = tid; u < 343; u += 256) {
            int n = u / 7, mg = u - n*7;
            u64t a2[7];
            #pragma unroll
            for (int mm=0;mm<7;mm++) a2[mm] = 0ull;
            for (int c = 0; c < C; c += 4) {
                const u64t* qp = (const u64t*)(Qs + n*XSTR + c);
                u64t q0 = qp[0], q1 = qp[1];
                #pragma unroll
                for (int mm=0;mm<7;mm++) {
                    const u64t* kp = (const u64t*)(Ks + (mg*7+mm)*XSTR + c);
                    a2[mm] = fma2(q0, kp[0], a2[mm]);
                    a2[mm] = fma2(q1, kp[1], a2[mm]);
                }
            }
            #pragma unroll
            for (int mm=0;mm<7;mm++) {
                float l,h; up2(a2[mm], l, h);
                Ss[n*SSTR + mg*7+mm] = (l+h)*scale;
            }
        }
    }
    __syncthreads();

    // ---- softmax rows (+ zero pad col 49) ----
    {
        const int lane = tid & 31, warp = tid >> 5;
        for (int n = warp; n < T; n += 8) {
            float v0 = Ss[n*SSTR + lane];
            float v1 = (lane < 17) ? Ss[n*SSTR + 32 + lane] : -3.0e38f;
            float m = fmaxf(v0, v1);
            #pragma unroll
            for (int o=16;o;o>>=1) m = fmaxf(m, __shfl_xor_sync(0xffffffffu, m, o));
            float e0 = __expf(v0 - m);
            float e1 = (lane < 17) ? __expf(v1 - m) : 0.f;
            float ssum = e0 + e1;
            #pragma unroll
            for (int o=16;o;o>>=1) ssum += __shfl_xor_sync(0xffffffffu, ssum, o);
            float inv = 1.f / ssum;
            Ss[n*SSTR + lane] = e0*inv;
            if (lane < 17) Ss[n*SSTR + 32 + lane] = e1*inv;
            if (lane == 17) Ss[n*SSTR + 49] = 0.f;
        }
    }
    __syncthreads();

    // ---- attn_out = S @ V -> XLN, contraction-packed over m pairs ----
    {
        const int cg = tid % 24, tg = tid / 24;   // tg<10 active, 5 rows each
        if (tg < 10) {
            u64t acc[5][4];
            #pragma unroll
            for (int i=0;i<5;i++)
                #pragma unroll
                for (int p=0;p<4;p++) acc[i][p] = 0ull;
            for (int m = 0; m < 50; m += 2) {
                float4 va = *(float4*)(Vs + m*XSTR + cg*4);
                float4 vb = *(float4*)(Vs + (m+1)*XSTR + cg*4);
                u64t v0 = pk2(va.x, vb.x), v1 = pk2(va.y, vb.y);
                u64t v2 = pk2(va.z, vb.z), v3 = pk2(va.w, vb.w);
                #pragma unroll
                for (int i=0;i<5;i++) {
                    u64t s2 = *(const u64t*)(Ss + (tg*5+i)*SSTR + m);
                    acc[i][0] = fma2(s2, v0, acc[i][0]);
                    acc[i][1] = fma2(s2, v1, acc[i][1]);
                    acc[i][2] = fma2(s2, v2, acc[i][2]);
                    acc[i][3] = fma2(s2, v3, acc[i][3]);
                }
            }
            #pragma unroll
            for (int i=0;i<5;i++) {
                float* d = XLN + (tg*5+i)*XSTR + cg*4;
                #pragma unroll
                for (int p=0;p<4;p++) {
                    float l,h; up2(acc[i][p], l, h);
                    d[p] = l + h;
                }
            }
        }
    }
    __syncthreads();

    // ---- MLP ----
    const int cg6 = tid % 32, tg8 = tid / 32;      // w1 map: 6 cols, 7 rows (all 256)
    const int cgf = tid % 24, tgf = tid / 24;      // w2 map: 4 cols, 5 rows (tgf<10)
    u64t facc[5][2];
    #pragma unroll
    for (int i=0;i<5;i++){ facc[i][0]=0ull; facc[i][1]=0ull; }

    for (int hc = 0; hc < 2; hc++) {
        const int j0 = hc * HCH;
        // --- hidden = gelu(attn_out @ w1[:, j0:j0+192] + b1) ---
        {
            u64t hacc[7][3];
            #pragma unroll
            for (int i=0;i<7;i++){ hacc[i][0]=0ull; hacc[i][1]=0ull; hacc[i][2]=0ull; }
            for (int c0 = 0; c0 < C; c0 += 16) {
                for (int i = tid; i < 768; i += 256) {         // 16 rows x 192 cols
                    int cc = i / 48, j4 = i - cc*48;
                    *(float4*)(Wst + cc*W1STR + j4*4) =
                        *(const float4*)(w1 + (size_t)(c0+cc)*HID + j0 + j4*4);
                }
                __syncthreads();
                #pragma unroll 4
                for (int cc=0;cc<16;cc++) {
                    u64t xs[7];
                    #pragma unroll
                    for (int i=0;i<7;i++) xs[i] = splat2(XLN[(tg8*7+i)*XSTR + c0+cc]);
                    const u64t* wp = (const u64t*)(Wst + cc*W1STR + cg6*6);
                    u64t w0=wp[0], w1v=wp[1], w2v=wp[2];
                    #pragma unroll
                    for (int i=0;i<7;i++) {
                        hacc[i][0] = fma2(xs[i], w0, hacc[i][0]);
                        hacc[i][1] = fma2(xs[i], w1v, hacc[i][1]);
                        hacc[i][2] = fma2(xs[i], w2v, hacc[i][2]);
                    }
                }
                __syncthreads();
            }
            {
                const float* bp = b1 + j0 + cg6*6;
                float bv[6];
                #pragma unroll
                for (int j=0;j<6;j++) bv[j] = bp[j];
                #pragma unroll
                for (int i=0;i<7;i++) {
                    float* hrow = HB + (tg8*7+i)*HSTR + cg6*6;
                    #pragma unroll
                    for (int p=0;p<3;p++) {
                        float l,h; up2(hacc[i][p], l, h);
                        float h0 = l + bv[2*p];
                        float h1 = h + bv[2*p+1];
                        hrow[2*p]   = 0.5f*h0*(1.f + erff(h0*0.70710678118654752f));
                        hrow[2*p+1] = 0.5f*h1*(1.f + erff(h1*0.70710678118654752f));
                    }
                }
            }
        }
        __syncthreads();
        // --- facc += hidden @ w2[j0:j0+192, :] ---
        for (int k0 = 0; k0 < HCH; k0 += 32) {
            for (int i = tid; i < 768; i += 256) {             // 32 rows x 96 cols
                int kk = i / 24, c4 = i - kk*24;
                *(float4*)(Wst + kk*W2STR + c4*4) =
                    *(const float4*)(w2 + (size_t)(j0+k0+kk)*C + c4*4);
            }
            __syncthreads();
            if (tgf < 10) {
                #pragma unroll 4
                for (int kk=0;kk<32;kk++) {
                    u64t hs[5];
                    #pragma unroll
                    for (int i=0;i<5;i++) hs[i] = splat2(HB[(tgf*5+i)*HSTR + k0+kk]);
                    const u64t* wp = (const u64t*)(Wst + kk*W2STR + cgf*4);
                    u64t w0=wp[0], w1v=wp[1];
                    #pragma unroll
                    for (int i=0;i<5;i++) {
                        facc[i][0] = fma2(hs[i], w0, facc[i][0]);
                        facc[i][1] = fma2(hs[i], w1v, facc[i][1]);
                    }
                }
            }
            __syncthreads();
        }
    }

    // ---- epilogue: + b2 + residual(attn_out), store ----
    if (tgf < 10) {
        float4 bb = *(const float4*)(b2 + cgf*4);
        #pragma unroll
        for (int i=0;i<5;i++) {
            int t = tgf*5 + i;
            if (t < 49) {
                int r = t / 7, s = t - r*7;
                const float* ao = XLN + t*XSTR + cgf*4;
                float l0,h0,l1,h1;
                up2(facc[i][0], l0, h0);
                up2(facc[i][1], l1, h1);
                float4 o;
                o.x = l0 + bb.x + ao[0];
                o.y = h0 + bb.y + ao[1];
                o.z = l1 + bb.z + ao[2];
                o.w = h1 + bb.w + ao[3];
                *(float4*)(out + base + (size_t)(r*HW + s)*C + cgf*4) = o;
            }
        }
    }
}

extern "C" void kernel_launch(void* const* d_in, const int* in_sizes, int n_in,
                              void* d_out, int out_size) {
    cudaFuncSetAttribute(swin_fused, cudaFuncAttributeMaxDynamicSharedMemorySize, SMEM_BYTES);
    swin_fused<<<8192, 256, SMEM_BYTES>>>(
        (const float*)d_in[0], (const float*)d_in[1], (const float*)d_in[2],
        (const float*)d_in[3], (const float*)d_in[4], (const float*)d_in[5],
        (const float*)d_in[6], (const float*)d_in[7], (float*)d_out);
}